// round 13
// baseline (speedup 1.0000x reference)
#include <cuda_runtime.h>
#include <cstdint>

#define NB   64
#define LQ   1024
#define LK   1024
#define DH   64
#define TQ   32          // query rows per CTA
#define KT   128         // key tile (cols per CTA pass; 16 per warp)
#define NT   256
#define NEG_BIG (-1.0e30f)

// XOR-swizzled [row][d] layouts, 16B granules g=0..15 within a 64-float row.
// bank-quad = (row*16 + g') mod 32 ; g' = g ^ ((row>>2)&7) makes the 8
// rows {r,r+4,...,r+28} (a-side) and 4 cols {4j+c} (b-side) conflict-free.
#define SQ_OFF(qi, g) (((qi) << 6) + ((((g) ^ (((qi) >> 2) & 7))) << 2))
#define SK_OFF(kj, g) (((kj) << 6) + ((((g) ^ (((kj) >> 2) & 7))) << 2))

// ---- packed fp32x2 helpers (sm_100 family feature, plain sm_103-safe) ----
__device__ __forceinline__ void ffma2(unsigned long long& d,
                                      unsigned long long a, unsigned long long b) {
    asm("fma.rn.f32x2 %0, %1, %2, %0;" : "+l"(d) : "l"(a), "l"(b));
}
__device__ __forceinline__ float2 unpack2(unsigned long long v) {
    float2 f;
    asm("mov.b64 {%0, %1}, %2;" : "=f"(f.x), "=f"(f.y) : "l"(v));
    return f;
}

__global__ __launch_bounds__(NT, 4)
void sparse_attn_kernel(const float* __restrict__ Q, const float* __restrict__ K,
                        const float* __restrict__ V, const int* __restrict__ M,
                        float* __restrict__ Out, float* __restrict__ Attn)
{
    __shared__ float s_q[TQ * DH];   // swizzled [qi][d], 8 KB
    __shared__ float s_k[KT * DH];   // swizzled [kj][d], 32 KB

    const int t    = threadIdx.x;
    const int b    = blockIdx.x >> 5;
    const int q0   = (blockIdx.x & 31) * TQ;
    const int warp = t >> 5, lane = t & 31;

    // ---- stage Q tile (scaled by 1/8, swizzled) : coalesced LDG.128, conflict-free STS.128
    const float* qg = Q + ((size_t)b * LQ + q0) * DH;
    for (int n = t; n < TQ * 16; n += NT) {
        int qi = n >> 4, g = n & 15;
        float4 f = *(const float4*)(qg + qi * DH + g * 4);
        f.x *= 0.125f; f.y *= 0.125f; f.z *= 0.125f; f.w *= 0.125f;
        *(float4*)(s_q + SQ_OFF(qi, g)) = f;
    }

    const int ig   = lane >> 2;          // row group: rows 4*ig .. 4*ig+3
    const int colw = warp * 16 + (lane & 3) * 4;   // 4 cols per lane

    float* zbase = Attn + ((size_t)b * LQ + q0) * LK;   // scores staged in attn buffer

    // ====== Phase 1: S = (Q/8) @ K^T -> gmem, d-pair packed FFMA2 ======
    const float* kg = K + (size_t)b * LK * DH;
    for (int kt = 0; kt < LK; kt += KT) {
        __syncthreads();
        for (int n = t; n < KT * 16; n += NT) {     // coalesced LDG, conflict-free STS
            int kj = n >> 4, g = n & 15;
            float4 f = *(const float4*)(kg + (size_t)(kt + kj) * DH + g * 4);
            *(float4*)(s_k + SK_OFF(kj, g)) = f;
        }
        __syncthreads();

        unsigned long long acc[4][4];
        #pragma unroll
        for (int r = 0; r < 4; r++)
            #pragma unroll
            for (int c = 0; c < 4; c++) acc[r][c] = 0ull;

        #pragma unroll
        for (int g = 0; g < 16; g++) {              // 4 d-values per g
            ulonglong2 b0 = *(const ulonglong2*)(s_k + SK_OFF(colw + 0, g));
            ulonglong2 b1 = *(const ulonglong2*)(s_k + SK_OFF(colw + 1, g));
            ulonglong2 b2 = *(const ulonglong2*)(s_k + SK_OFF(colw + 2, g));
            ulonglong2 b3 = *(const ulonglong2*)(s_k + SK_OFF(colw + 3, g));
            #pragma unroll
            for (int r = 0; r < 4; r++) {
                ulonglong2 a = *(const ulonglong2*)(s_q + SQ_OFF(ig * 4 + r, g));
                ffma2(acc[r][0], a.x, b0.x); ffma2(acc[r][0], a.y, b0.y);
                ffma2(acc[r][1], a.x, b1.x); ffma2(acc[r][1], a.y, b1.y);
                ffma2(acc[r][2], a.x, b2.x); ffma2(acc[r][2], a.y, b2.y);
                ffma2(acc[r][3], a.x, b3.x); ffma2(acc[r][3], a.y, b3.y);
            }
        }
        #pragma unroll
        for (int r = 0; r < 4; r++) {
            float2 f0 = unpack2(acc[r][0]), f1 = unpack2(acc[r][1]);
            float2 f2 = unpack2(acc[r][2]), f3 = unpack2(acc[r][3]);
            *(float4*)(zbase + (size_t)(ig * 4 + r) * LK + kt + colw) =
                make_float4(f0.x + f0.y, f1.x + f1.y, f2.x + f2.y, f3.x + f3.y);
        }
    }

    __syncthreads();   // rows' columns span warps now -> CTA-wide visibility

    // ======= Phase 2+3 fused, per warp: mask + sparsemax + sparse P@V =======
    const float* vg = V + (size_t)b * LK * DH;
    const int*   mbase = M + ((size_t)b * LQ + q0) * LK;
    const int qi0 = warp * 4;   // phase-2/3 row ownership (reads via gmem staging)

    for (int r = 0; r < 4; r++) {
        const int row = qi0 + r;
        float*     z  = zbase + (size_t)row * LK;
        const int* mr = mbase + (size_t)row * LK;

        float4 zr[8];
        float S = 0.0f; int n = 0;
        #pragma unroll
        for (int j = 0; j < 8; j++) {
            float4 zz = *(const float4*)(z  + j * 128 + lane * 4);
            int4   mm = *(const int4*)  (mr + j * 128 + lane * 4);
            zz.x = mm.x ? NEG_BIG : zz.x;
            zz.y = mm.y ? NEG_BIG : zz.y;
            zz.z = mm.z ? NEG_BIG : zz.z;
            zz.w = mm.w ? NEG_BIG : zz.w;
            zr[j] = zz;
            if (zz.x > -5.0e29f) { S += zz.x; n++; }
            if (zz.y > -5.0e29f) { S += zz.y; n++; }
            if (zz.z > -5.0e29f) { S += zz.z; n++; }
            if (zz.w > -5.0e29f) { S += zz.w; n++; }
        }
        #pragma unroll
        for (int o = 16; o; o >>= 1) {
            S += __shfl_xor_sync(0xffffffffu, S, o);
            n += __shfl_xor_sync(0xffffffffu, n, o);
        }

        float tau;
        if (n == 0) {
            tau = 3.0e38f;                       // fully-masked row -> p = 0 everywhere
        } else {
            tau = (S - 1.0f) / (float)n;
            for (int it = 0; it < 64; it++) {    // Michelot fixed point (exact)
                float S2 = 0.0f; int n2 = 0;
                #pragma unroll
                for (int j = 0; j < 8; j++) {
                    float4 zz = zr[j];
                    if (zz.x > tau) { S2 += zz.x; n2++; }
                    if (zz.y > tau) { S2 += zz.y; n2++; }
                    if (zz.z > tau) { S2 += zz.z; n2++; }
                    if (zz.w > tau) { S2 += zz.w; n2++; }
                }
                #pragma unroll
                for (int o = 16; o; o >>= 1) {
                    S2 += __shfl_xor_sync(0xffffffffu, S2, o);
                    n2 += __shfl_xor_sync(0xffffffffu, n2, o);
                }
                if (n2 >= n) break;
                n = n2;
                tau = (S2 - 1.0f) / (float)n2;
            }
        }

        float2 oacc = make_float2(0.0f, 0.0f);
        #pragma unroll
        for (int j = 0; j < 8; j++) {
            float4 p;
            p.x = fmaxf(zr[j].x - tau, 0.0f);
            p.y = fmaxf(zr[j].y - tau, 0.0f);
            p.z = fmaxf(zr[j].z - tau, 0.0f);
            p.w = fmaxf(zr[j].w - tau, 0.0f);
            *(float4*)(z + j * 128 + lane * 4) = p;   // attn output (overwrites z)

            bool any = (p.x > 0.0f) | (p.y > 0.0f) | (p.z > 0.0f) | (p.w > 0.0f);
            unsigned bal = __ballot_sync(0xffffffffu, any);
            while (bal) {
                int L = __ffs(bal) - 1;
                bal &= bal - 1;
                float px = __shfl_sync(0xffffffffu, p.x, L);
                float py = __shfl_sync(0xffffffffu, p.y, L);
                float pz = __shfl_sync(0xffffffffu, p.z, L);
                float pw = __shfl_sync(0xffffffffu, p.w, L);
                const int kb = j * 128 + L * 4;
                if (px > 0.0f) {
                    float2 vv = *(const float2*)(vg + (size_t)(kb + 0) * DH + 2 * lane);
                    oacc.x += px * vv.x; oacc.y += px * vv.y;
                }
                if (py > 0.0f) {
                    float2 vv = *(const float2*)(vg + (size_t)(kb + 1) * DH + 2 * lane);
                    oacc.x += py * vv.x; oacc.y += py * vv.y;
                }
                if (pz > 0.0f) {
                    float2 vv = *(const float2*)(vg + (size_t)(kb + 2) * DH + 2 * lane);
                    oacc.x += pz * vv.x; oacc.y += pz * vv.y;
                }
                if (pw > 0.0f) {
                    float2 vv = *(const float2*)(vg + (size_t)(kb + 3) * DH + 2 * lane);
                    oacc.x += pw * vv.x; oacc.y += pw * vv.y;
                }
            }
        }

        *(float2*)(Out + ((size_t)b * LQ + q0 + row) * DH + 2 * lane) = oacc;
    }
}

extern "C" void kernel_launch(void* const* d_in, const int* in_sizes, int n_in,
                              void* d_out, int out_size)
{
    const float* q = (const float*)d_in[0];
    const float* k = (const float*)d_in[1];
    const float* v = (const float*)d_in[2];
    const int*   m = (const int*)d_in[3];

    float* out  = (float*)d_out;                 // [B, Lq, D]
    float* attn = out + (size_t)NB * LQ * DH;    // [B, Lq, Lk]

    dim3 grid(NB * (LQ / TQ));   // 2048 CTAs
    sparse_attn_kernel<<<grid, NT>>>(q, k, v, m, out, attn);
}

// round 17
// speedup vs baseline: 1.5434x; 1.5434x over previous
#include <cuda_runtime.h>
#include <cuda_bf16.h>
#include <cstdint>

#define NB   64
#define LQ   1024
#define LK   1024
#define DH   64
#define TQ   32          // query rows per CTA
#define KT   128         // key tile; 16 cols per warp
#define NT   256
#define NEG_BIG (-1.0e30f)
#define LDM  72          // bf16 row stride for planes (16B-aligned, conflict-free ldmatrix)

__device__ __forceinline__ uint32_t smem_u32(const void* p) {
    uint32_t a;
    asm("{ .reg .u64 t; cvta.to.shared.u64 t, %1; cvt.u32.u64 %0, t; }" : "=r"(a) : "l"(p));
    return a;
}
#define LDSM4(r, a) \
    asm volatile("ldmatrix.sync.aligned.m8n8.x4.shared.b16 {%0,%1,%2,%3}, [%4];" \
        : "=r"((r)[0]), "=r"((r)[1]), "=r"((r)[2]), "=r"((r)[3]) : "r"(a))
#define LDSM2(r, a) \
    asm volatile("ldmatrix.sync.aligned.m8n8.x2.shared.b16 {%0,%1}, [%2];" \
        : "=r"((r)[0]), "=r"((r)[1]) : "r"(a))

__device__ __forceinline__ void mma_bf16(float* d, const uint32_t* a, const uint32_t* b) {
    asm volatile("mma.sync.aligned.m16n8k16.row.col.f32.bf16.bf16.f32 "
        "{%0,%1,%2,%3}, {%4,%5,%6,%7}, {%8,%9}, {%0,%1,%2,%3};"
        : "+f"(d[0]), "+f"(d[1]), "+f"(d[2]), "+f"(d[3])
        : "r"(a[0]), "r"(a[1]), "r"(a[2]), "r"(a[3]), "r"(b[0]), "r"(b[1]));
}

// split 4 floats into hi/lo bf16 pairs and store (2x u32 per plane)
__device__ __forceinline__ void split_store(__nv_bfloat16* ph, __nv_bfloat16* pl, float4 f) {
    __nv_bfloat162 h01 = __float22bfloat162_rn(make_float2(f.x, f.y));
    __nv_bfloat162 h23 = __float22bfloat162_rn(make_float2(f.z, f.w));
    uint32_t u01 = *(uint32_t*)&h01, u23 = *(uint32_t*)&h23;
    float hx = __uint_as_float(u01 << 16),  hy = __uint_as_float(u01 & 0xffff0000u);
    float hz = __uint_as_float(u23 << 16),  hw = __uint_as_float(u23 & 0xffff0000u);
    __nv_bfloat162 l01 = __float22bfloat162_rn(make_float2(f.x - hx, f.y - hy));
    __nv_bfloat162 l23 = __float22bfloat162_rn(make_float2(f.z - hz, f.w - hw));
    ((uint32_t*)ph)[0] = u01;             ((uint32_t*)ph)[1] = u23;
    ((uint32_t*)pl)[0] = *(uint32_t*)&l01; ((uint32_t*)pl)[1] = *(uint32_t*)&l23;
}

__global__ __launch_bounds__(NT, 4)
void sparse_attn_kernel(const float* __restrict__ Q, const float* __restrict__ K,
                        const float* __restrict__ V, const int* __restrict__ M,
                        float* __restrict__ Out, float* __restrict__ Attn)
{
    __shared__ __nv_bfloat16 s_qh[TQ * LDM], s_ql[TQ * LDM];   // 4.6 KB x2
    __shared__ __nv_bfloat16 s_kh[KT * LDM], s_kl[KT * LDM];   // 18.4 KB x2

    const int t    = threadIdx.x;
    const int b    = blockIdx.x >> 5;
    const int q0   = (blockIdx.x & 31) * TQ;
    const int warp = t >> 5, lane = t & 31;

    // ---- stage Q tile: scaled by 1/8, hi/lo bf16 split ----
    const float* qg = Q + ((size_t)b * LQ + q0) * DH;
    for (int n = t; n < TQ * 16; n += NT) {
        int row = n >> 4, g = n & 15;
        float4 f = *(const float4*)(qg + row * DH + g * 4);
        f.x *= 0.125f; f.y *= 0.125f; f.z *= 0.125f; f.w *= 0.125f;
        split_store(s_qh + row * LDM + g * 4, s_ql + row * LDM + g * 4, f);
    }

    float* zbase = Attn + ((size_t)b * LQ + q0) * LK;

    // ldmatrix source offsets (element units)
    const int a_off = (lane & 15) * LDM + ((lane >> 4) << 3);        // row, col-half
    const int b_off = (warp * 16 + (lane & 7)) * LDM + (((lane >> 3) & 1) << 3);
    const int g8 = lane >> 2, c2 = (lane & 3) * 2;

    // ====== Phase 1: S = (Q/8) @ K^T via mma.sync bf16 (hi/lo split) ======
    const float* kg = K + (size_t)b * LK * DH;
    for (int kt = 0; kt < LK; kt += KT) {
        __syncthreads();
        for (int n = t; n < KT * 16; n += NT) {     // coalesced LDG.128, split to planes
            int row = n >> 4, g = n & 15;
            float4 f = *(const float4*)(kg + (size_t)(kt + row) * DH + g * 4);
            split_store(s_kh + row * LDM + g * 4, s_kl + row * LDM + g * 4, f);
        }
        __syncthreads();

        float acc[2][2][4];
        #pragma unroll
        for (int mt = 0; mt < 2; mt++)
            #pragma unroll
            for (int nt = 0; nt < 2; nt++)
                #pragma unroll
                for (int i = 0; i < 4; i++) acc[mt][nt][i] = 0.0f;

        #pragma unroll
        for (int kc = 0; kc < 4; kc++) {
            uint32_t ah[2][4], al[2][4], bh[2][2], bl[2][2];
            #pragma unroll
            for (int mt = 0; mt < 2; mt++) {
                LDSM4(ah[mt], smem_u32(s_qh + (mt * 16) * LDM + kc * 16 + a_off));
                LDSM4(al[mt], smem_u32(s_ql + (mt * 16) * LDM + kc * 16 + a_off));
            }
            #pragma unroll
            for (int nt = 0; nt < 2; nt++) {
                LDSM2(bh[nt], smem_u32(s_kh + (nt * 8) * LDM + kc * 16 + b_off));
                LDSM2(bl[nt], smem_u32(s_kl + (nt * 8) * LDM + kc * 16 + b_off));
            }
            #pragma unroll
            for (int mt = 0; mt < 2; mt++)
                #pragma unroll
                for (int nt = 0; nt < 2; nt++) {
                    mma_bf16(acc[mt][nt], ah[mt], bh[nt]);   // hi*hi
                    mma_bf16(acc[mt][nt], ah[mt], bl[nt]);   // hi*lo
                    mma_bf16(acc[mt][nt], al[mt], bh[nt]);   // lo*hi
                }
        }

        // store fragments: rows mt*16+g8 (+8), cols kt + warp*16 + nt*8 + c2 (+1)
        #pragma unroll
        for (int mt = 0; mt < 2; mt++)
            #pragma unroll
            for (int nt = 0; nt < 2; nt++) {
                float* p = zbase + (size_t)(mt * 16 + g8) * LK + kt + warp * 16 + nt * 8 + c2;
                *(float2*)p            = make_float2(acc[mt][nt][0], acc[mt][nt][1]);
                *(float2*)(p + 8 * LK) = make_float2(acc[mt][nt][2], acc[mt][nt][3]);
            }
    }

    __syncthreads();   // scores for our phase-2 rows were written by other warps

    // ======= Phase 2+3 fused (R12 proven): mask + sparsemax + sparse P@V =======
    const float* vg = V + (size_t)b * LK * DH;
    const int*   mbase = M + ((size_t)b * LQ + q0) * LK;
    const int qi0 = warp * 4;

    for (int r = 0; r < 4; r++) {
        const int row = qi0 + r;
        float*     z  = zbase + (size_t)row * LK;
        const int* mr = mbase + (size_t)row * LK;

        float4 zr[8];
        float S = 0.0f; int n = 0;
        #pragma unroll
        for (int j = 0; j < 8; j++) {
            float4 zz = *(const float4*)(z  + j * 128 + lane * 4);
            int4   mm = *(const int4*)  (mr + j * 128 + lane * 4);
            zz.x = mm.x ? NEG_BIG : zz.x;
            zz.y = mm.y ? NEG_BIG : zz.y;
            zz.z = mm.z ? NEG_BIG : zz.z;
            zz.w = mm.w ? NEG_BIG : zz.w;
            zr[j] = zz;
            if (zz.x > -5.0e29f) { S += zz.x; n++; }
            if (zz.y > -5.0e29f) { S += zz.y; n++; }
            if (zz.z > -5.0e29f) { S += zz.z; n++; }
            if (zz.w > -5.0e29f) { S += zz.w; n++; }
        }
        #pragma unroll
        for (int o = 16; o; o >>= 1) {
            S += __shfl_xor_sync(0xffffffffu, S, o);
            n += __shfl_xor_sync(0xffffffffu, n, o);
        }

        float tau;
        if (n == 0) {
            tau = 3.0e38f;
        } else {
            tau = (S - 1.0f) / (float)n;
            for (int it = 0; it < 64; it++) {    // Michelot fixed point (exact)
                float S2 = 0.0f; int n2 = 0;
                #pragma unroll
                for (int j = 0; j < 8; j++) {
                    float4 zz = zr[j];
                    if (zz.x > tau) { S2 += zz.x; n2++; }
                    if (zz.y > tau) { S2 += zz.y; n2++; }
                    if (zz.z > tau) { S2 += zz.z; n2++; }
                    if (zz.w > tau) { S2 += zz.w; n2++; }
                }
                #pragma unroll
                for (int o = 16; o; o >>= 1) {
                    S2 += __shfl_xor_sync(0xffffffffu, S2, o);
                    n2 += __shfl_xor_sync(0xffffffffu, n2, o);
                }
                if (n2 >= n) break;
                n = n2;
                tau = (S2 - 1.0f) / (float)n2;
            }
        }

        float2 oacc = make_float2(0.0f, 0.0f);
        #pragma unroll
        for (int j = 0; j < 8; j++) {
            float4 p;
            p.x = fmaxf(zr[j].x - tau, 0.0f);
            p.y = fmaxf(zr[j].y - tau, 0.0f);
            p.z = fmaxf(zr[j].z - tau, 0.0f);
            p.w = fmaxf(zr[j].w - tau, 0.0f);
            *(float4*)(z + j * 128 + lane * 4) = p;   // attn output

            bool any = (p.x > 0.0f) | (p.y > 0.0f) | (p.z > 0.0f) | (p.w > 0.0f);
            unsigned bal = __ballot_sync(0xffffffffu, any);
            while (bal) {
                int L = __ffs(bal) - 1;
                bal &= bal - 1;
                float px = __shfl_sync(0xffffffffu, p.x, L);
                float py = __shfl_sync(0xffffffffu, p.y, L);
                float pz = __shfl_sync(0xffffffffu, p.z, L);
                float pw = __shfl_sync(0xffffffffu, p.w, L);
                const int kb = j * 128 + L * 4;
                if (px > 0.0f) {
                    float2 vv = *(const float2*)(vg + (size_t)(kb + 0) * DH + 2 * lane);
                    oacc.x += px * vv.x; oacc.y += px * vv.y;
                }
                if (py > 0.0f) {
                    float2 vv = *(const float2*)(vg + (size_t)(kb + 1) * DH + 2 * lane);
                    oacc.x += py * vv.x; oacc.y += py * vv.y;
                }
                if (pz > 0.0f) {
                    float2 vv = *(const float2*)(vg + (size_t)(kb + 2) * DH + 2 * lane);
                    oacc.x += pz * vv.x; oacc.y += pz * vv.y;
                }
                if (pw > 0.0f) {
                    float2 vv = *(const float2*)(vg + (size_t)(kb + 3) * DH + 2 * lane);
                    oacc.x += pw * vv.x; oacc.y += pw * vv.y;
                }
            }
        }

        *(float2*)(Out + ((size_t)b * LQ + q0 + row) * DH + 2 * lane) = oacc;
    }
}

extern "C" void kernel_launch(void* const* d_in, const int* in_sizes, int n_in,
                              void* d_out, int out_size)
{
    const float* q = (const float*)d_in[0];
    const float* k = (const float*)d_in[1];
    const float* v = (const float*)d_in[2];
    const int*   m = (const int*)d_in[3];

    float* out  = (float*)d_out;                 // [B, Lq, D]
    float* attn = out + (size_t)NB * LQ * DH;    // [B, Lq, Lk]

    dim3 grid(NB * (LQ / TQ));   // 2048 CTAs
    sparse_attn_kernel<<<grid, NT>>>(q, k, v, m, out, attn);
}